// round 8
// baseline (speedup 1.0000x reference)
#include <cuda_runtime.h>
#include <math.h>

#define T_LEN     1048576
#define MAXO      25
#define CLAMP_HI  24.0f
#define SEG       4
#define NTHREADS  256
#define NWARP     (NTHREADS/32)
#define PER_BLOCK (SEG*NTHREADS)       /* 1024 */
#define NB        (T_LEN/PER_BLOCK)    /* 1024 tiles */
#define K1_THREADS 512
#define K1_ELEMS   16
#define K1_BLOCKS  (T_LEN/(K1_THREADS*K1_ELEMS))        /* 128 */
#define TILES_PER_K1 ((K1_THREADS*K1_ELEMS)/PER_BLOCK)  /* 8 */
#define FPT       (NB/NTHREADS)        /* 4 fns per thread in global scan */
#define FULLM     0xffffffffu

struct Fn { float a, b, c; };

__device__ Fn g_blockF[NB];

__device__ __forceinline__ Fn fn_identity() { return Fn{0.f, -1e30f, 1e30f}; }

// f1 applied first, then f2:  (f2 o f1)(x) = min(max(x+a, b), c)
__device__ __forceinline__ Fn fn_compose(Fn f1, Fn f2) {
    Fn r;
    r.a = f1.a + f2.a;
    r.b = fmaxf(f1.b + f2.a, f2.b);
    r.c = fminf(fmaxf(f1.c + f2.a, f2.b), f2.c);
    return r;
}

__device__ __forceinline__ float fn_apply(Fn f, float x) {
    return fminf(fmaxf(x + f.a, f.b), f.c);
}

__device__ __forceinline__ Fn warp_incl_scan(Fn v, int lane) {
    #pragma unroll
    for (int off = 1; off < 32; off <<= 1) {
        float pa = __shfl_up_sync(FULLM, v.a, off);
        float pb = __shfl_up_sync(FULLM, v.b, off);
        float pc = __shfl_up_sync(FULLM, v.c, off);
        if (lane >= off) v = fn_compose(Fn{pa, pb, pc}, v);
    }
    return v;
}

// ---------------------------------------------------------------------------
// K1: 128 blocks x 512 threads, 16 elems/thread -> 8 tile functions per block
// ---------------------------------------------------------------------------
__global__ void __launch_bounds__(K1_THREADS)
k1_block_totals(const int* __restrict__ seq, const float* __restrict__ delta) {
    __shared__ float dl[16];
    __shared__ Fn warpTot[K1_THREADS / 32];   // 16
    int tid = threadIdx.x, lane = tid & 31, wid = tid >> 5;
    if (tid < 16) dl[tid] = delta[tid];
    __syncthreads();

    const int4* p = (const int4*)(seq + (size_t)blockIdx.x * (K1_THREADS * K1_ELEMS)
                                      + tid * K1_ELEMS);
    int4 w0 = p[0], w1 = p[1], w2 = p[2], w3 = p[3];
    int vals[16] = {w0.x, w0.y, w0.z, w0.w, w1.x, w1.y, w1.z, w1.w,
                    w2.x, w2.y, w2.z, w2.w, w3.x, w3.y, w3.z, w3.w};

    Fn f = fn_identity();
    #pragma unroll
    for (int i = 0; i < 16; i++) {
        float d = dl[vals[i]];
        f.a += d;
        f.b = fmaxf(f.b + d, 0.f);
        f.c = fminf(fmaxf(f.c + d, 0.f), CLAMP_HI);
    }
    Fn inc = warp_incl_scan(f, lane);
    if (lane == 31) warpTot[wid] = inc;
    __syncthreads();
    // one warp = 512 elems; one 1024-elem tile = 2 consecutive warps
    if (tid < TILES_PER_K1) {
        Fn t = fn_compose(warpTot[tid * 2], warpTot[tid * 2 + 1]);
        g_blockF[blockIdx.x * TILES_PER_K1 + tid] = t;
    }
}

// ---------------------------------------------------------------------------
// K3: global prefix recompute + counters in registers + factored softmax
//     with float2-packed tables + per-warp staged coalesced streaming writes.
// ---------------------------------------------------------------------------
__global__ void __launch_bounds__(NTHREADS)
k3_output(const int* __restrict__ seq, const float* __restrict__ delta,
          const float* __restrict__ bias, const float* __restrict__ scale,
          float* __restrict__ out) {
    __shared__ float dl[16];
    __shared__ float An[MAXO], Ap[MAXO];
    __shared__ __align__(8) float2 Anp[MAXO];       // (An[j], Ap[j])
    __shared__ __align__(8) float2 SP[MAXO + 1];    // (SufAn[k], PreAp[k])
    __shared__ Fn    warpTotG[NWARP];
    __shared__ Fn    warpTot[NWARP];
    __shared__ float s_start;
    __shared__ __align__(16) float stage[NTHREADS * MAXO];  // 25.6 KB

    int tid = threadIdx.x, lane = tid & 31, wid = tid >> 5, bid = blockIdx.x;
    float s = scale[0];
    if (tid < 16) dl[tid] = delta[tid];
    if (tid < MAXO) {
        float fj = (float)tid;
        float an = expf(bias[tid] - s * fj);   // j >= c path (* e^{ s c})
        float ap = expf(bias[tid] + s * fj);   // j <  c path (* e^{-s c})
        An[tid] = an;
        Ap[tid] = ap;
        Anp[tid] = make_float2(an, ap);
    }

    // issue seq loads early
    const int4* p = (const int4*)(seq + (size_t)bid * PER_BLOCK + tid * SEG);
    int4 v0 = p[0];

    // load this thread's FPT=4 global tile functions (L2-hot)
    Fn g4[FPT];
    #pragma unroll
    for (int i = 0; i < FPT; i++) g4[i] = g_blockF[FPT * tid + i];
    __syncthreads();

    if (tid == 0) {
        float a = 0.f, b = 0.f;
        // SP[k] = (sum_{j>=k} An[j], sum_{j<k} Ap[j])
        float suf[MAXO + 1];
        suf[MAXO] = 0.f;
        for (int k = MAXO - 1; k >= 0; k--) { a += An[k]; suf[k] = a; }
        for (int k = 0; k <= MAXO; k++) {
            SP[k] = make_float2(suf[k], b);
            if (k < MAXO) b += Ap[k];
        }
    }

    // ---- block-wide scan over the 1024 tile functions (4 per thread) ----
    Fn quad = g4[0];
    #pragma unroll
    for (int i = 1; i < FPT; i++) quad = fn_compose(quad, g4[i]);
    Fn incG = warp_incl_scan(quad, lane);
    if (lane == 31) warpTotG[wid] = incG;
    __syncthreads();
    if (wid == 0) {
        Fn v = (lane < NWARP) ? warpTotG[lane] : fn_identity();
        #pragma unroll
        for (int off = 1; off < NWARP; off <<= 1) {
            float pa = __shfl_up_sync(FULLM, v.a, off);
            float pb = __shfl_up_sync(FULLM, v.b, off);
            float pc = __shfl_up_sync(FULLM, v.c, off);
            if (lane >= off) v = fn_compose(Fn{pa, pb, pc}, v);
        }
        if (lane < NWARP) warpTotG[lane] = v;
    }
    __syncthreads();
    {
        float pa = __shfl_up_sync(FULLM, incG.a, 1);
        float pb = __shfl_up_sync(FULLM, incG.b, 1);
        float pc = __shfl_up_sync(FULLM, incG.c, 1);
        Fn lane_excl = (lane == 0) ? fn_identity() : Fn{pa, pb, pc};
        Fn wexcl     = (wid  == 0) ? fn_identity() : warpTotG[wid - 1];
        Fn exclG = fn_compose(wexcl, lane_excl);   // prefix of fns [0, FPT*tid)
        if (tid == (bid >> 2)) {
            Fn e = exclG;
            #pragma unroll
            for (int i = 0; i < FPT - 1; i++)
                if (i < (bid & 3)) e = fn_compose(e, g4[i]);
            s_start = fn_apply(e, 0.f);
        }
    }

    // ---- per-thread fn over its 4 symbols ----
    int vals[SEG] = {v0.x, v0.y, v0.z, v0.w};
    float dv[SEG];
    Fn f = fn_identity();
    #pragma unroll
    for (int i = 0; i < SEG; i++) {
        float d = dl[vals[i]];
        dv[i] = d;
        f.a += d;
        f.b = fmaxf(f.b + d, 0.f);
        f.c = fminf(fmaxf(f.c + d, 0.f), CLAMP_HI);
    }

    // ---- block scan of thread functions ----
    Fn inc = warp_incl_scan(f, lane);
    if (lane == 31) warpTot[wid] = inc;
    __syncthreads();                                // also publishes s_start, SP
    if (wid == 0) {
        Fn v = (lane < NWARP) ? warpTot[lane] : fn_identity();
        #pragma unroll
        for (int off = 1; off < NWARP; off <<= 1) {
            float pa = __shfl_up_sync(FULLM, v.a, off);
            float pb = __shfl_up_sync(FULLM, v.b, off);
            float pc = __shfl_up_sync(FULLM, v.c, off);
            if (lane >= off) v = fn_compose(Fn{pa, pb, pc}, v);
        }
        if (lane < NWARP) warpTot[lane] = v;
    }
    __syncthreads();
    float pa = __shfl_up_sync(FULLM, inc.a, 1);
    float pb = __shfl_up_sync(FULLM, inc.b, 1);
    float pc = __shfl_up_sync(FULLM, inc.c, 1);
    Fn lane_excl = (lane == 0) ? fn_identity() : Fn{pa, pb, pc};
    Fn wexcl     = (wid  == 0) ? fn_identity() : warpTot[wid - 1];
    Fn excl = fn_compose(wexcl, lane_excl);

    // ---- exact sequential recurrence; counters stay in REGISTERS ----
    float cr[SEG];
    {
        float c = fn_apply(excl, s_start);
        #pragma unroll
        for (int i = 0; i < SEG; i++) {
            c = fminf(fmaxf(c + dv[i], 0.f), CLAMP_HI);
            cr[i] = c;
        }
    }

    // ---- per-warp softmax + staged coalesced streaming writes ----
    float* wstage = stage + wid * (32 * MAXO);
    size_t outbase = ((size_t)bid * PER_BLOCK + wid * (PER_BLOCK / NWARP)) * (size_t)MAXO;
    int e = lane & 3;

    #pragma unroll 1
    for (int batch = 0; batch < PER_BLOCK / NWARP / 32; batch++) {
        // fetch the counter for row (wid*128 + batch*32 + lane) from its
        // owner lane within this warp: src = batch*8 + (lane>>2), elem = lane&3
        int src = batch * 8 + (lane >> 2);
        float t0 = __shfl_sync(FULLM, cr[0], src);
        float t1 = __shfl_sync(FULLM, cr[1], src);
        float t2 = __shfl_sync(FULLM, cr[2], src);
        float t3 = __shfl_sync(FULLM, cr[3], src);
        float cc = (e == 0) ? t0 : (e == 1) ? t1 : (e == 2) ? t2 : t3;

        int   k   = (int)ceilf(cc);
        float ec  = __expf(s * cc);
        float emc = __expf(-s * cc);
        float2 sp = SP[k];
        float sum = ec * sp.x + emc * sp.y;
        float inv = __fdividef(1.0f, sum);
        float eci = ec * inv, emci = emc * inv;
        #pragma unroll
        for (int j = 0; j < MAXO; j++) {
            float2 ap = Anp[j];
            wstage[lane * MAXO + j] = (j >= k) ? ap.x * eci : ap.y * emci;
        }
        __syncwarp();

        const float4* ss = (const float4*)wstage;
        float4* dd = (float4*)(out + outbase + (size_t)batch * (32 * MAXO));
        #pragma unroll
        for (int q = lane; q < 32 * MAXO / 4; q += 32) __stcs(dd + q, ss[q]);
        __syncwarp();
    }
}

// ---------------------------------------------------------------------------
extern "C" void kernel_launch(void* const* d_in, const int* in_sizes, int n_in,
                              void* d_out, int out_size) {
    const int*   seq   = (const int*)  d_in[0];
    const float* delta = (const float*)d_in[1];
    const float* bias  = (const float*)d_in[2];
    const float* scale = (const float*)d_in[3];
    float* out = (float*)d_out;

    k1_block_totals<<<K1_BLOCKS, K1_THREADS>>>(seq, delta);
    k3_output<<<NB, NTHREADS>>>(seq, delta, bias, scale, out);
}